// round 2
// baseline (speedup 1.0000x reference)
#include <cuda_runtime.h>

#define N_NODES 10000
#define N_EDGES 320000
#define HID 128
#define H3 384
#define NRBF 20

// scratch: node MLP output x = silu(q@W1+b1)@W2+b2, [N, 384]
__device__ float g_x[N_NODES * H3];
__device__ int g_idx64;

__device__ __forceinline__ float silu_f(float v) {
    return v / (1.0f + __expf(-v));
}

__device__ __forceinline__ unsigned long long pack2(float lo, float hi) {
    unsigned long long r;
    asm("mov.b64 %0,{%1,%2};" : "=l"(r) : "f"(lo), "f"(hi));
    return r;
}
__device__ __forceinline__ void unpack2(unsigned long long v, float& lo, float& hi) {
    asm("mov.b64 {%0,%1},%2;" : "=f"(lo), "=f"(hi) : "l"(v));
}
// packed f32x2 FMA — ptxas never emits this from C++, 2x fma-pipe throughput
__device__ __forceinline__ unsigned long long fma2(unsigned long long a,
                                                   unsigned long long b,
                                                   unsigned long long c) {
    unsigned long long d;
    asm("fma.rn.f32x2 %0,%1,%2,%3;" : "=l"(d) : "l"(a), "l"(b), "l"(c));
    return d;
}
// vector atomic: 1 red op covers 4 floats (sm_90+)
__device__ __forceinline__ void red_add_v4(float* p, float4 v) {
    asm volatile("red.global.add.v4.f32 [%0],{%1,%2,%3,%4};"
                 :: "l"(p), "f"(v.x), "f"(v.y), "f"(v.z), "f"(v.w) : "memory");
}

// ---------------------------------------------------------------------------
// Kernel 1: out = concat(q, mu); also detect int32 vs int64 edge_index layout.
// ---------------------------------------------------------------------------
__global__ void init_out(const float* __restrict__ q,
                         const float* __restrict__ mu,
                         float* __restrict__ out,
                         const int* __restrict__ ei32) {
    if (blockIdx.x == 0 && threadIdx.x == 0) {
        // If edge_index is int64, every odd 32-bit word of the first row is the
        // high word of a small positive index == 0. If int32, these are random
        // node ids; all-16-zero has probability ~1e-64.
        int flag = 1;
        #pragma unroll
        for (int i = 0; i < 16; i++)
            if (ei32[2 * i + 1] != 0) flag = 0;
        g_idx64 = flag;
    }
    int i = blockIdx.x * blockDim.x + threadIdx.x;
    const int nq4 = N_NODES * HID / 4;
    const int nm4 = N_NODES * H3 / 4;
    float4* o4 = (float4*)out;
    if (i < nq4)            o4[i] = ((const float4*)q)[i];
    else if (i < nq4 + nm4) o4[i] = ((const float4*)mu)[i - nq4];
}

// ---------------------------------------------------------------------------
// Kernel 2: node MLP  x = silu(q@W1+b1)@W2+b2  -> g_x [N, 384]
// 16 nodes per block; each thread owns output column(s), so each weight LDG
// is reused across 16 node accumulators.
// ---------------------------------------------------------------------------
__global__ __launch_bounds__(256) void node_mlp(const float* __restrict__ q,
                                                const float* __restrict__ W1,
                                                const float* __restrict__ b1,
                                                const float* __restrict__ W2,
                                                const float* __restrict__ b2) {
    __shared__ float qs[16 * HID];   // 8 KB
    __shared__ float t1s[16 * H3];   // 24 KB
    const int n0 = blockIdx.x * 16;
    const int tid = threadIdx.x;

    for (int i = tid; i < 16 * HID; i += 256) qs[i] = q[n0 * HID + i];
    __syncthreads();

    // layer 1: [16,128] @ [128,384] + b1 -> silu -> t1s
    for (int c = tid; c < H3; c += 256) {
        float acc[16];
        float bb = __ldg(&b1[c]);
        #pragma unroll
        for (int n = 0; n < 16; n++) acc[n] = bb;
        for (int k = 0; k < HID; k++) {
            float w = __ldg(&W1[k * H3 + c]);
            #pragma unroll
            for (int n = 0; n < 16; n++) acc[n] += qs[n * HID + k] * w;
        }
        #pragma unroll
        for (int n = 0; n < 16; n++) t1s[n * H3 + c] = silu_f(acc[n]);
    }
    __syncthreads();

    // layer 2: [16,384] @ [384,384] + b2 -> g_x
    for (int c = tid; c < H3; c += 256) {
        float acc[16];
        float bb = __ldg(&b2[c]);
        #pragma unroll
        for (int n = 0; n < 16; n++) acc[n] = bb;
        for (int k = 0; k < H3; k++) {
            float w = __ldg(&W2[k * H3 + c]);
            #pragma unroll
            for (int n = 0; n < 16; n++) acc[n] += t1s[n * H3 + k] * w;
        }
        #pragma unroll
        for (int n = 0; n < 16; n++) g_x[(n0 + n) * H3 + c] = acc[n];
    }
}

// ---------------------------------------------------------------------------
// Kernel 3: fused edge kernel. Per block of 32 edges:
//   A) h1 = silu(rbf @ Wf1 + bf1) into smem [32,128]
//   B) filters = (h1 @ Wf2 + bf2) * cutoff  — outer-product form, f32x2 packed
//      accumulators; Wf2 rows read coalesced (no transpose needed)
//   C) epilogue: gather x[src], mu[src]; scatter messages via red.add.v4.f32
// Each warp owns 4 edges x all 384 columns (lane -> 4 consecutive cols/part).
// ---------------------------------------------------------------------------
__global__ __launch_bounds__(256) void edge_kernel(
        const int* __restrict__ ei32, const long long* __restrict__ ei64,
        const float* __restrict__ rbf, const float* __restrict__ uv,
        const float* __restrict__ cut,
        const float* __restrict__ Wf1, const float* __restrict__ bf1,
        const float* __restrict__ Wf2, const float* __restrict__ bf2,
        const float* __restrict__ mu, float* __restrict__ out) {
    __shared__ float h1s[32][HID];        // 16 KB
    __shared__ float Wf1s[NRBF * HID];    // 10 KB
    __shared__ float rbfs[32 * NRBF];     // 2.5 KB
    __shared__ float bf1s[HID];
    __shared__ float bf2s[H3];
    __shared__ float cuts[32];
    __shared__ float uvs[32][3];
    __shared__ int srcs[32], tgts[32];

    const int tid = threadIdx.x;
    const int e0 = blockIdx.x * 32;
    const int idx64 = g_idx64;

    for (int i = tid; i < NRBF * HID; i += 256) Wf1s[i] = Wf1[i];
    for (int i = tid; i < 32 * NRBF; i += 256)  rbfs[i] = rbf[e0 * NRBF + i];
    for (int i = tid; i < H3; i += 256)         bf2s[i] = bf2[i];
    if (tid < HID) bf1s[tid] = bf1[tid];
    if (tid >= 192 && tid < 224) {
        int i = tid - 192;
        int e = e0 + i;
        cuts[i] = cut[e];
        if (idx64) { tgts[i] = (int)ei64[e]; srcs[i] = (int)ei64[N_EDGES + e]; }
        else       { tgts[i] = ei32[e];      srcs[i] = ei32[N_EDGES + e]; }
    }
    if (tid >= 64 && tid < 160) {
        int i = tid - 64;
        uvs[i / 3][i % 3] = uv[e0 * 3 + i];
    }
    __syncthreads();

    // Phase A: h1 (K = 20 is tiny)
    for (int i = tid; i < 32 * HID; i += 256) {
        int e = i >> 7, j = i & 127;
        float a = bf1s[j];
        #pragma unroll
        for (int k = 0; k < NRBF; k++) a += rbfs[e * NRBF + k] * Wf1s[k * HID + j];
        h1s[e][j] = silu_f(a);
    }
    __syncthreads();

    // Phase B: filter GEMM. lane covers cols [lane*4, lane*4+4) of each part.
    const int warp = tid >> 5, lane = tid & 31;
    const int eb = warp * 4;

    unsigned long long acc[4][6];
    #pragma unroll
    for (int a = 0; a < 4; a++)
        #pragma unroll
        for (int b = 0; b < 6; b++) acc[a][b] = 0ull;

    const ulonglong2* W2v = (const ulonglong2*)Wf2;  // 96 ulonglong2 per row
    #pragma unroll 4
    for (int k = 0; k < HID; k++) {
        const ulonglong2* row = W2v + k * 96;
        ulonglong2 wq = __ldg(row + lane);        // part q  (cols   0..127)
        ulonglong2 wr = __ldg(row + 32 + lane);   // part r  (cols 128..255)
        ulonglong2 wm = __ldg(row + 64 + lane);   // part mu (cols 256..383)
        #pragma unroll
        for (int e4 = 0; e4 < 4; e4++) {
            float h = h1s[eb + e4][k];
            unsigned long long h2 = pack2(h, h);
            acc[e4][0] = fma2(h2, wq.x, acc[e4][0]);
            acc[e4][1] = fma2(h2, wq.y, acc[e4][1]);
            acc[e4][2] = fma2(h2, wr.x, acc[e4][2]);
            acc[e4][3] = fma2(h2, wr.y, acc[e4][3]);
            acc[e4][4] = fma2(h2, wm.x, acc[e4][4]);
            acc[e4][5] = fma2(h2, wm.y, acc[e4][5]);
        }
    }

    // Phase C: epilogue — bias + cutoff, gather, scatter
    const float4* xv  = (const float4*)g_x;  // 96 float4 per node row
    const float4* muv = (const float4*)mu;   // 32 float4 per (node,d) row
    float* outq  = out;
    float* outmu = out + N_NODES * HID;
    const int c4 = lane * 4;

    #pragma unroll
    for (int e4 = 0; e4 < 4; e4++) {
        const int e = eb + e4;
        const float cscale = cuts[e];
        const int src = srcs[e], tgt = tgts[e];

        float fq[4], fr[4], fm[4];
        unpack2(acc[e4][0], fq[0], fq[1]); unpack2(acc[e4][1], fq[2], fq[3]);
        unpack2(acc[e4][2], fr[0], fr[1]); unpack2(acc[e4][3], fr[2], fr[3]);
        unpack2(acc[e4][4], fm[0], fm[1]); unpack2(acc[e4][5], fm[2], fm[3]);
        #pragma unroll
        for (int i = 0; i < 4; i++) {
            fq[i] = (fq[i] + bf2s[c4 + i]) * cscale;
            fr[i] = (fr[i] + bf2s[HID + c4 + i]) * cscale;
            fm[i] = (fm[i] + bf2s[2 * HID + c4 + i]) * cscale;
        }

        // scalar message
        float4 xq = __ldg(xv + src * 96 + lane);
        red_add_v4(outq + tgt * HID + c4,
                   make_float4(xq.x * fq[0], xq.y * fq[1], xq.z * fq[2], xq.w * fq[3]));

        // vector message
        float4 xr = __ldg(xv + src * 96 + 32 + lane);
        float4 xm = __ldg(xv + src * 96 + 64 + lane);
        float xr0 = xr.x * fr[0], xr1 = xr.y * fr[1], xr2 = xr.z * fr[2], xr3 = xr.w * fr[3];
        float xm0 = xm.x * fm[0], xm1 = xm.y * fm[1], xm2 = xm.z * fm[2], xm3 = xm.w * fm[3];
        #pragma unroll
        for (int d = 0; d < 3; d++) {
            float u = uvs[e][d];
            float4 m4 = __ldg(muv + (src * 3 + d) * 32 + lane);
            red_add_v4(outmu + (tgt * 3 + d) * HID + c4,
                       make_float4(u * xr0 + m4.x * xm0,
                                   u * xr1 + m4.y * xm1,
                                   u * xr2 + m4.z * xm2,
                                   u * xr3 + m4.w * xm3));
        }
    }
}

extern "C" void kernel_launch(void* const* d_in, const int* in_sizes, int n_in,
                              void* d_out, int out_size) {
    const float* q   = (const float*)d_in[0];
    const float* mu  = (const float*)d_in[1];
    const void*  ei  = d_in[2];
    const float* rbf = (const float*)d_in[3];
    const float* uvp = (const float*)d_in[4];
    const float* cut = (const float*)d_in[5];
    const float* W1  = (const float*)d_in[6];
    const float* b1  = (const float*)d_in[7];
    const float* W2  = (const float*)d_in[8];
    const float* b2  = (const float*)d_in[9];
    const float* Wf1 = (const float*)d_in[10];
    const float* bf1 = (const float*)d_in[11];
    const float* Wf2 = (const float*)d_in[12];
    const float* bf2 = (const float*)d_in[13];
    float* out = (float*)d_out;

    const int total4 = N_NODES * (HID + H3) / 4;
    init_out<<<(total4 + 255) / 256, 256>>>(q, mu, out, (const int*)ei);
    node_mlp<<<N_NODES / 16, 256>>>(q, W1, b1, W2, b2);
    edge_kernel<<<N_EDGES / 32, 256>>>((const int*)ei, (const long long*)ei,
                                       rbf, uvp, cut, Wf1, bf1, Wf2, bf2, mu, out);
}